// round 1
// baseline (speedup 1.0000x reference)
#include <cuda_runtime.h>
#include <math.h>

#define ED   1024
#define GH   1024
#define NLAY 3
#define NHEAD 8
#define HDIM 128
#define NNODE 2048
#define BB   1024
#define TEMPR 0.05f
#define LAPW 0.1f

// ---------------- scratch (device globals; no allocation allowed) ----------------
__device__ float g_x[NNODE * GH];        // evolving node state
__device__ float g_Wh[NNODE * GH];       // per-layer Wh (heads concatenated)
__device__ float g_Wcat[ED * GH];        // transposed gatW for current layer
__device__ float g_s1[NHEAD * NNODE];
__device__ float g_s2[NHEAD * NNODE];
__device__ float g_hb[NNODE * GH];       // attention output
__device__ int   g_cnt[NNODE];
__device__ int   g_off[NNODE + 1];
__device__ int   g_cols[NNODE * 256];    // total nnz ~85k << capacity
__device__ float g_ge[NNODE * ED];       // graph embeds
__device__ float g_t[NNODE * ED];        // poW gemm out / laplacian@g
__device__ float g_tmp1[BB * ED];
__device__ float g_tmp2[BB * ED];
__device__ float g_q[BB * ED];
__device__ float g_p[BB * ED];
__device__ float g_neg[BB * BB];
__device__ float g_rowv[BB];
__device__ float g_part[256];
__device__ float g_scal[2];

// ---------------- SGEMM: C = A @ B (or A @ B^T), all dims multiple of 128 --------
__global__ __launch_bounds__(256, 2)
void sgemm_k(const float* __restrict__ A, const float* __restrict__ B,
             float* __restrict__ C, int M, int Nc, int K, int transB)
{
    __shared__ __align__(16) float As[8][128];
    __shared__ __align__(16) float Bs[8][128];
    int tid = threadIdx.x;
    int tx = tid & 15, ty = tid >> 4;
    int rowBase = blockIdx.y * 128;
    int colBase = blockIdx.x * 128;

    float acc[8][8];
#pragma unroll
    for (int i = 0; i < 8; i++)
#pragma unroll
        for (int j = 0; j < 8; j++) acc[i][j] = 0.f;

    for (int k0 = 0; k0 < K; k0 += 8) {
        int idx = tid * 4;
        int ar = idx >> 3, ak = idx & 7;
        float4 av = *(const float4*)(A + (size_t)(rowBase + ar) * K + k0 + ak);
        As[ak + 0][ar] = av.x; As[ak + 1][ar] = av.y;
        As[ak + 2][ar] = av.z; As[ak + 3][ar] = av.w;

        if (!transB) {
            int bk = idx >> 7, bc = idx & 127;
            float4 bv = *(const float4*)(B + (size_t)(k0 + bk) * Nc + colBase + bc);
            *(float4*)&Bs[bk][bc] = bv;
        } else {
            int bc = idx >> 3, bk = idx & 7;
            float4 bv = *(const float4*)(B + (size_t)(colBase + bc) * K + k0 + bk);
            Bs[bk + 0][bc] = bv.x; Bs[bk + 1][bc] = bv.y;
            Bs[bk + 2][bc] = bv.z; Bs[bk + 3][bc] = bv.w;
        }
        __syncthreads();

#pragma unroll
        for (int kk = 0; kk < 8; kk++) {
            float a[8], b[8];
            float4 a0 = *(const float4*)&As[kk][ty * 8];
            float4 a1 = *(const float4*)&As[kk][ty * 8 + 4];
            float4 b0 = *(const float4*)&Bs[kk][tx * 8];
            float4 b1 = *(const float4*)&Bs[kk][tx * 8 + 4];
            a[0]=a0.x; a[1]=a0.y; a[2]=a0.z; a[3]=a0.w; a[4]=a1.x; a[5]=a1.y; a[6]=a1.z; a[7]=a1.w;
            b[0]=b0.x; b[1]=b0.y; b[2]=b0.z; b[3]=b0.w; b[4]=b1.x; b[5]=b1.y; b[6]=b1.z; b[7]=b1.w;
#pragma unroll
            for (int i = 0; i < 8; i++)
#pragma unroll
                for (int j = 0; j < 8; j++) acc[i][j] = fmaf(a[i], b[j], acc[i][j]);
        }
        __syncthreads();
    }

#pragma unroll
    for (int i = 0; i < 8; i++) {
        size_t row = rowBase + ty * 8 + i;
        float4 c0 = make_float4(acc[i][0], acc[i][1], acc[i][2], acc[i][3]);
        float4 c1 = make_float4(acc[i][4], acc[i][5], acc[i][6], acc[i][7]);
        *(float4*)(C + row * Nc + colBase + tx * 8)     = c0;
        *(float4*)(C + row * Nc + colBase + tx * 8 + 4) = c1;
    }
}

// ---------------- gatW[l] -> Wcat [ED, GH] --------------------------------------
__global__ void kTransposeGat(const float* __restrict__ gatW, float* __restrict__ Wcat, int l)
{
    int idx = blockIdx.x * 256 + threadIdx.x;   // ED*GH threads
    int f = idx >> 10;
    int rem = idx & 1023;
    int h = rem >> 7, o = rem & 127;
    Wcat[idx] = gatW[(((size_t)l * NHEAD + h) * ED + f) * HDIM + o];
}

// ---------------- s1/s2: warp per (n,h) dot over HD=128 --------------------------
__global__ void kComputeS(const float* __restrict__ Wh, const float* __restrict__ a1,
                          const float* __restrict__ a2, float* s1, float* s2)
{
    int w = (blockIdx.x * blockDim.x + threadIdx.x) >> 5;
    int lane = threadIdx.x & 31;
    int n = w >> 3, h = w & 7;
    float4 v  = *(const float4*)(Wh + (size_t)n * GH + h * HDIM + lane * 4);
    float4 x1 = *(const float4*)(a1 + h * HDIM + lane * 4);
    float4 x2 = *(const float4*)(a2 + h * HDIM + lane * 4);
    float d1 = v.x * x1.x + v.y * x1.y + v.z * x1.z + v.w * x1.w;
    float d2 = v.x * x2.x + v.y * x2.y + v.z * x2.z + v.w * x2.w;
#pragma unroll
    for (int o = 16; o; o >>= 1) {
        d1 += __shfl_xor_sync(~0u, d1, o);
        d2 += __shfl_xor_sync(~0u, d2, o);
    }
    if (!lane) { s1[h * NNODE + n] = d1; s2[h * NNODE + n] = d2; }
}

// ---------------- CSR build ------------------------------------------------------
__global__ void kCsrCount(const float* __restrict__ adj, int* cnt)
{
    int w = (blockIdx.x * blockDim.x + threadIdx.x) >> 5;
    int lane = threadIdx.x & 31;
    if (w >= NNODE) return;
    int c = 0;
    for (int j = lane; j < NNODE; j += 32) c += (adj[(size_t)w * NNODE + j] > 0.f);
#pragma unroll
    for (int o = 16; o; o >>= 1) c += __shfl_xor_sync(~0u, c, o);
    if (!lane) cnt[w] = c;
}

__global__ void kScan(const int* __restrict__ cnt, int* off)
{
    __shared__ int sh[257];
    int t = threadIdx.x;               // 256
    int base = t * 8;
    int local[8], s = 0;
#pragma unroll
    for (int i = 0; i < 8; i++) { local[i] = cnt[base + i]; s += local[i]; }
    sh[t] = s;
    __syncthreads();
    if (t == 0) {
        int run = 0;
        for (int i = 0; i < 256; i++) { int v = sh[i]; sh[i] = run; run += v; }
        sh[256] = run;
    }
    __syncthreads();
    int run = sh[t];
#pragma unroll
    for (int i = 0; i < 8; i++) { off[base + i] = run; run += local[i]; }
    if (t == 255) off[NNODE] = sh[256];
}

__global__ void kCsrFill(const float* __restrict__ adj, const int* __restrict__ off, int* cols)
{
    int w = (blockIdx.x * blockDim.x + threadIdx.x) >> 5;
    int lane = threadIdx.x & 31;
    if (w >= NNODE) return;
    int base = off[w];
    for (int c0 = 0; c0 < NNODE; c0 += 32) {
        bool p = adj[(size_t)w * NNODE + c0 + lane] > 0.f;
        unsigned m = __ballot_sync(~0u, p);
        if (p) cols[base + __popc(m & ((1u << lane) - 1u))] = c0 + lane;
        base += __popc(m);
    }
}

// ---------------- sparse GAT attention: warp h of block n ------------------------
__global__ void kAttn(const float* __restrict__ Wh, const float* __restrict__ s1,
                      const float* __restrict__ s2, const int* __restrict__ off,
                      const int* __restrict__ cols, float* __restrict__ out)
{
    int n = blockIdx.x;
    int h = threadIdx.x >> 5, lane = threadIdx.x & 31;
    int o0 = off[n], o1 = off[n + 1];
    float sv = s1[h * NNODE + n];

    float mx = -INFINITY;
    for (int i = o0 + lane; i < o1; i += 32) {
        float e = sv + s2[h * NNODE + cols[i]];
        e = e > 0.f ? e : 0.2f * e;
        mx = fmaxf(mx, e);
    }
#pragma unroll
    for (int o = 16; o; o >>= 1) mx = fmaxf(mx, __shfl_xor_sync(~0u, mx, o));

    float a0 = 0.f, a1 = 0.f, a2 = 0.f, a3 = 0.f, sum = 0.f;
    for (int i = o0; i < o1; i++) {
        int j = cols[i];
        float e = sv + s2[h * NNODE + j];
        e = e > 0.f ? e : 0.2f * e;
        float wgt = expf(e - mx);
        sum += wgt;
        float4 v = *(const float4*)(Wh + (size_t)j * GH + h * HDIM + lane * 4);
        a0 = fmaf(wgt, v.x, a0); a1 = fmaf(wgt, v.y, a1);
        a2 = fmaf(wgt, v.z, a2); a3 = fmaf(wgt, v.w, a3);
    }
    float inv = 1.f / sum;
    float4 r = make_float4(a0 * inv, a1 * inv, a2 * inv, a3 * inv);
    *(float4*)(out + (size_t)n * GH + h * HDIM + lane * 4) = r;
}

// ---------------- block reductions helper pattern in-kernel ----------------------
__device__ __forceinline__ float blockReduceSum(float v, float* red)
{
    int t = threadIdx.x;
    red[t] = v; __syncthreads();
    for (int st = 128; st; st >>= 1) { if (t < st) red[t] += red[t + st]; __syncthreads(); }
    float r = red[0];
    __syncthreads();
    return r;
}

// x += elu(layernorm(hin)); row per block, 256 threads
__global__ void kLnEluRes(const float* __restrict__ hin, const float* __restrict__ g,
                          const float* __restrict__ b, float* __restrict__ x)
{
    __shared__ float red[256];
    int n = blockIdx.x, t = threadIdx.x;
    float4 v = ((const float4*)(hin + (size_t)n * GH))[t];
    float mu = blockReduceSum(v.x + v.y + v.z + v.w, red) * (1.f / GH);
    float dx0 = v.x - mu, dx1 = v.y - mu, dx2 = v.z - mu, dx3 = v.w - mu;
    float var = blockReduceSum(dx0*dx0 + dx1*dx1 + dx2*dx2 + dx3*dx3, red) * (1.f / GH);
    float rs = rsqrtf(var + 1e-5f);
    int c = t * 4;
    float4 gg = *(const float4*)(g + c), bb = *(const float4*)(b + c);
    float y0 = dx0 * rs * gg.x + bb.x, y1 = dx1 * rs * gg.y + bb.y;
    float y2 = dx2 * rs * gg.z + bb.z, y3 = dx3 * rs * gg.w + bb.w;
    y0 = y0 > 0.f ? y0 : expm1f(y0); y1 = y1 > 0.f ? y1 : expm1f(y1);
    y2 = y2 > 0.f ? y2 : expm1f(y2); y3 = y3 > 0.f ? y3 : expm1f(y3);
    float4* xp = (float4*)(x + (size_t)n * GH) + t;
    float4 xv = *xp;
    xv.x += y0; xv.y += y1; xv.z += y2; xv.w += y3;
    *xp = xv;
}

// out = gelu(layernorm(C + b1; g, beta)); row per block
__global__ void kLnGelu(const float* __restrict__ C, const float* __restrict__ b1,
                        const float* __restrict__ g, const float* __restrict__ beta,
                        float* __restrict__ out)
{
    __shared__ float red[256];
    int n = blockIdx.x, t = threadIdx.x;
    int c = t * 4;
    float4 v = ((const float4*)(C + (size_t)n * ED))[t];
    float4 bv = *(const float4*)(b1 + c);
    v.x += bv.x; v.y += bv.y; v.z += bv.z; v.w += bv.w;
    float mu = blockReduceSum(v.x + v.y + v.z + v.w, red) * (1.f / ED);
    float d0 = v.x - mu, d1 = v.y - mu, d2 = v.z - mu, d3 = v.w - mu;
    float var = blockReduceSum(d0*d0 + d1*d1 + d2*d2 + d3*d3, red) * (1.f / ED);
    float rs = rsqrtf(var + 1e-5f);
    float4 gg = *(const float4*)(g + c), be = *(const float4*)(beta + c);
    float y0 = d0 * rs * gg.x + be.x, y1 = d1 * rs * gg.y + be.y;
    float y2 = d2 * rs * gg.z + be.z, y3 = d3 * rs * gg.w + be.w;
    const float k = 0.70710678118654752f;
    y0 = 0.5f * y0 * (1.f + erff(y0 * k)); y1 = 0.5f * y1 * (1.f + erff(y1 * k));
    y2 = 0.5f * y2 * (1.f + erff(y2 * k)); y3 = 0.5f * y3 * (1.f + erff(y3 * k));
    ((float4*)(out + (size_t)n * ED))[t] = make_float4(y0, y1, y2, y3);
}

// out = l2norm(C + b2); row per block
__global__ void kBiasL2(const float* __restrict__ C, const float* __restrict__ b2,
                        float* __restrict__ out)
{
    __shared__ float red[256];
    int n = blockIdx.x, t = threadIdx.x;
    int c = t * 4;
    float4 v = ((const float4*)(C + (size_t)n * ED))[t];
    float4 bv = *(const float4*)(b2 + c);
    v.x += bv.x; v.y += bv.y; v.z += bv.z; v.w += bv.w;
    float ss = blockReduceSum(v.x*v.x + v.y*v.y + v.z*v.z + v.w*v.w, red);
    float inv = 1.f / fmaxf(sqrtf(ss), 1e-12f);
    ((float4*)(out + (size_t)n * ED))[t] = make_float4(v.x*inv, v.y*inv, v.z*inv, v.w*inv);
}

// ge = C + pob (broadcast over rows)
__global__ void kBiasAdd(const float* __restrict__ C, const float* __restrict__ bias,
                         float* __restrict__ out, int ncols, int total)
{
    int i = blockIdx.x * 256 + threadIdx.x;
    if (i < total) out[i] = C[i] + bias[i % ncols];
}

// rowv[i] = logsumexp([pos_i, neg_i,:]/T) - pos_i/T
__global__ void kLse(const float* __restrict__ neg, float* __restrict__ rowv)
{
    __shared__ float red[256];
    int i = blockIdx.x, t = threadIdx.x;
    const float invT = 1.f / TEMPR;
    float pos = neg[(size_t)i * BB + i] * invT;
    float4 v = ((const float4*)(neg + (size_t)i * BB))[t];
    v.x *= invT; v.y *= invT; v.z *= invT; v.w *= invT;
    float m = fmaxf(fmaxf(v.x, v.y), fmaxf(v.z, v.w));
    m = fmaxf(m, pos);
    red[t] = m; __syncthreads();
    for (int st = 128; st; st >>= 1) { if (t < st) red[t] = fmaxf(red[t], red[t + st]); __syncthreads(); }
    float M = red[0];
    __syncthreads();
    float s = expf(v.x - M) + expf(v.y - M) + expf(v.z - M) + expf(v.w - M);
    float S = blockReduceSum(s, red);
    if (t == 0) rowv[i] = M + logf(S + expf(pos - M)) - pos;
}

__global__ void kMeanRow(const float* __restrict__ rowv, float* scal)
{
    __shared__ float red[256];
    int t = threadIdx.x;
    float s = rowv[t] + rowv[t + 256] + rowv[t + 512] + rowv[t + 768];
    float S = blockReduceSum(s, red);
    if (t == 0) scal[0] = S / (float)BB;
}

__global__ void kDotPart(const float* __restrict__ a, const float* __restrict__ b,
                         float* part, int n)
{
    __shared__ float red[256];
    float s = 0.f;
    for (int i = blockIdx.x * 256 + threadIdx.x; i < n; i += 256 * 256) s = fmaf(a[i], b[i], s);
    float S = blockReduceSum(s, red);
    if (threadIdx.x == 0) part[blockIdx.x] = S;
}

__global__ void kDotFinal(const float* __restrict__ part, float* scal)
{
    __shared__ float red[256];
    float S = blockReduceSum(part[threadIdx.x], red);
    if (threadIdx.x == 0) scal[1] = S / (float)NNODE;
}

__global__ void kFinal(const float* __restrict__ scal, float* out, int n)
{
    if (threadIdx.x == 0) {
        float inf_nce = scal[0], lap = scal[1];
        if (n > 0) out[0] = inf_nce + LAPW * lap;
        if (n > 1) out[1] = inf_nce;
        if (n > 2) out[2] = lap;
    }
}

// ---------------- host -----------------------------------------------------------
static inline void* sym(const void* s) { void* p = nullptr; cudaGetSymbolAddress(&p, s); return p; }

extern "C" void kernel_launch(void* const* d_in, const int* in_sizes, int n_in,
                              void* d_out, int out_size)
{
    const float* query = (const float*)d_in[0];
    const float* docs  = (const float*)d_in[1];
    const float* nodes = (const float*)d_in[2];
    const float* adj   = (const float*)d_in[3];
    const float* lapM  = (const float*)d_in[4];
    const float* qW1 = (const float*)d_in[5];  const float* qb1 = (const float*)d_in[6];
    const float* qg  = (const float*)d_in[7];  const float* qbt = (const float*)d_in[8];
    const float* qW2 = (const float*)d_in[9];  const float* qb2 = (const float*)d_in[10];
    const float* dW1 = (const float*)d_in[11]; const float* db1 = (const float*)d_in[12];
    const float* dg  = (const float*)d_in[13]; const float* dbt = (const float*)d_in[14];
    const float* dW2 = (const float*)d_in[15]; const float* db2 = (const float*)d_in[16];
    const float* gatW = (const float*)d_in[17];
    const float* a1 = (const float*)d_in[18];
    const float* a2 = (const float*)d_in[19];
    const float* ln_g = (const float*)d_in[20];
    const float* ln_b = (const float*)d_in[21];
    const float* poW = (const float*)d_in[22];
    const float* pob = (const float*)d_in[23];

    float* x    = (float*)sym(g_x);
    float* Wh   = (float*)sym(g_Wh);
    float* Wcat = (float*)sym(g_Wcat);
    float* s1   = (float*)sym(g_s1);
    float* s2   = (float*)sym(g_s2);
    float* hb   = (float*)sym(g_hb);
    int*   cnt  = (int*)sym(g_cnt);
    int*   off  = (int*)sym(g_off);
    int*   cols = (int*)sym(g_cols);
    float* ge   = (float*)sym(g_ge);
    float* tb   = (float*)sym(g_t);
    float* tmp1 = (float*)sym(g_tmp1);
    float* tmp2 = (float*)sym(g_tmp2);
    float* q    = (float*)sym(g_q);
    float* p    = (float*)sym(g_p);
    float* neg  = (float*)sym(g_neg);
    float* rowv = (float*)sym(g_rowv);
    float* part = (float*)sym(g_part);
    float* scal = (float*)sym(g_scal);

    // init node state
    cudaMemcpyAsync(x, nodes, (size_t)NNODE * ED * sizeof(float), cudaMemcpyDeviceToDevice);

    // CSR from adj
    kCsrCount<<<NNODE / 8, 256>>>(adj, cnt);
    kScan<<<1, 256>>>(cnt, off);
    kCsrFill<<<NNODE / 8, 256>>>(adj, off, cols);

    dim3 gN(GH / 128, NNODE / 128);   // [2048 x 1024] outputs
    dim3 gB(ED / 128, BB / 128);      // [1024 x 1024] outputs

    for (int l = 0; l < NLAY; l++) {
        kTransposeGat<<<(ED * GH) / 256, 256>>>(gatW, Wcat, l);
        sgemm_k<<<gN, 256>>>(x, Wcat, Wh, NNODE, GH, ED, 0);
        kComputeS<<<(NNODE * NHEAD) / 8, 256>>>(Wh, a1 + (size_t)l * NHEAD * HDIM,
                                                a2 + (size_t)l * NHEAD * HDIM, s1, s2);
        kAttn<<<NNODE, 256>>>(Wh, s1, s2, off, cols, hb);
        kLnEluRes<<<NNODE, 256>>>(hb, ln_g + (size_t)l * GH, ln_b + (size_t)l * GH, x);
    }

    // graph embeds = x @ poW + pob
    sgemm_k<<<gN, 256>>>(x, poW, tb, NNODE, ED, GH, 0);
    kBiasAdd<<<(NNODE * ED) / 256, 256>>>(tb, pob, ge, ED, NNODE * ED);

    // query tower
    sgemm_k<<<gB, 256>>>(query, qW1, tmp1, BB, ED, ED, 0);
    kLnGelu<<<BB, 256>>>(tmp1, qb1, qg, qbt, tmp2);
    sgemm_k<<<gB, 256>>>(tmp2, qW2, tmp1, BB, ED, ED, 0);
    kBiasL2<<<BB, 256>>>(tmp1, qb2, q);

    // doc tower
    sgemm_k<<<gB, 256>>>(docs, dW1, tmp1, BB, ED, ED, 0);
    kLnGelu<<<BB, 256>>>(tmp1, db1, dg, dbt, tmp2);
    sgemm_k<<<gB, 256>>>(tmp2, dW2, tmp1, BB, ED, ED, 0);
    kBiasL2<<<BB, 256>>>(tmp1, db2, p);

    // similarities + InfoNCE
    sgemm_k<<<dim3(BB / 128, BB / 128), 256>>>(q, p, neg, BB, BB, ED, 1);
    kLse<<<BB, 256>>>(neg, rowv);
    kMeanRow<<<1, 256>>>(rowv, scal);

    // laplacian term
    sgemm_k<<<gN, 256>>>(lapM, ge, tb, NNODE, ED, NNODE, 0);
    kDotPart<<<256, 256>>>(ge, tb, part, NNODE * ED);
    kDotFinal<<<1, 256>>>(part, scal);

    kFinal<<<1, 32>>>(scal, (float*)d_out, out_size);
}

// round 2
// speedup vs baseline: 3.4822x; 3.4822x over previous
#include <cuda_runtime.h>
#include <math.h>
#include <stdint.h>

#define ED   1024
#define GH   1024
#define NLAY 3
#define NHEAD 8
#define HDIM 128
#define NNODE 2048
#define BB   1024
#define TEMPR 0.05f
#define LAPW 0.1f

// ---------------- scratch (device globals; no allocation allowed) ----------------
__device__ float g_x[NNODE * GH];        // evolving node state (fp32)
__device__ float g_xr[NNODE * GH];       // tf32-rounded copy of A operands
__device__ float g_Wh[NNODE * GH];       // per-layer Wh (heads concatenated)
__device__ float g_Wcat[GH * ED];        // B^T (rounded) for current GAT layer
__device__ float g_wT[ED * GH];          // transposed+rounded weight scratch
__device__ float g_lapr[NNODE * NNODE];  // rounded laplacian
__device__ float g_geT[ED * NNODE];      // rounded transposed graph embeds
__device__ float g_s1[NHEAD * NNODE];
__device__ float g_s2[NHEAD * NNODE];
__device__ float g_hb[NNODE * GH];       // attention output
__device__ int   g_cnt[NNODE];
__device__ int   g_off[NNODE + 1];
__device__ int   g_cols[NNODE * 256];
__device__ float g_ge[NNODE * ED];       // graph embeds (fp32)
__device__ float g_t[NNODE * ED];        // gemm out scratch
__device__ float g_tmp1[BB * ED];
__device__ float g_tmp2[BB * ED];
__device__ float g_q[BB * ED];
__device__ float g_p[BB * ED];
__device__ float g_neg[BB * BB];
__device__ float g_rowv[BB];
__device__ float g_part[256];
__device__ float g_scal[2];

// ---------------- tf32 helpers ---------------------------------------------------
__device__ __forceinline__ float tf32r(float x)
{
    float y;
    asm("cvt.rna.tf32.f32 %0, %1;" : "=f"(y) : "f"(x));
    return y;
}

__device__ __forceinline__ void mma_tf32(float* d, const float* a, const float* b)
{
    asm volatile(
        "mma.sync.aligned.m16n8k8.row.col.f32.tf32.tf32.f32 "
        "{%0,%1,%2,%3}, {%4,%5,%6,%7}, {%8,%9}, {%0,%1,%2,%3};\n"
        : "+f"(d[0]), "+f"(d[1]), "+f"(d[2]), "+f"(d[3])
        : "r"(__float_as_uint(a[0])), "r"(__float_as_uint(a[1])),
          "r"(__float_as_uint(a[2])), "r"(__float_as_uint(a[3])),
          "r"(__float_as_uint(b[0])), "r"(__float_as_uint(b[1])));
}

__device__ __forceinline__ void cpasync16(uint32_t dst, const void* src)
{
    asm volatile("cp.async.cg.shared.global [%0], [%1], 16;\n" :: "r"(dst), "l"(src));
}

// ---------------- tf32 tensor-core GEMM: C[M,N] = A[M,K] @ Bt[N,K]^T -------------
#define BM 128
#define BN 128
#define BK 32
#define SPAD 36                       // BK + 4 pad -> conflict-free fragment LDS
#define SBUF (128 * SPAD)             // floats per stage per operand
#define GEMM_SMEM (4 * SBUF * 4)      // bytes: 2 stages x (A + B)

__global__ __launch_bounds__(256)
void gemm_tf32(const float* __restrict__ A, const float* __restrict__ Bt,
               float* __restrict__ C, int M, int N, int K)
{
    extern __shared__ float sm[];
    const int tid = threadIdx.x;
    const int lane = tid & 31, warp = tid >> 5;
    const int wm = warp >> 2, wn = warp & 3;       // 2 x 4 warp grid
    const int lq = lane >> 2, lr = lane & 3;
    const int rowBase = blockIdx.y * BM;
    const int colBase = blockIdx.x * BN;

    const uint32_t smBase = (uint32_t)__cvta_generic_to_shared(sm);

    float acc[4][4][4];
#pragma unroll
    for (int i = 0; i < 4; i++)
#pragma unroll
        for (int j = 0; j < 4; j++)
#pragma unroll
            for (int r = 0; r < 4; r++) acc[i][j][r] = 0.f;

    const int ntiles = K / BK;

    auto issue = [&](int kt, int buf) {
#pragma unroll
        for (int c = 0; c < 4; c++) {
            int idx = tid + c * 256;          // 0..1023
            int r = idx >> 3;                  // 0..127
            int k4 = (idx & 7) * 4;            // 0,4,...,28
            const float* ga = A + (size_t)(rowBase + r) * K + kt * BK + k4;
            cpasync16(smBase + (uint32_t)((buf * SBUF + r * SPAD + k4) * 4), ga);
            const float* gb = Bt + (size_t)(colBase + r) * K + kt * BK + k4;
            cpasync16(smBase + (uint32_t)(((2 + buf) * SBUF + r * SPAD + k4) * 4), gb);
        }
        asm volatile("cp.async.commit_group;\n");
    };

    issue(0, 0);

    for (int kt = 0; kt < ntiles; kt++) {
        int buf = kt & 1;
        if (kt + 1 < ntiles) {
            issue(kt + 1, buf ^ 1);
            asm volatile("cp.async.wait_group 1;\n");
        } else {
            asm volatile("cp.async.wait_group 0;\n");
        }
        __syncthreads();

        const float* as = sm + buf * SBUF;
        const float* bs = sm + (2 + buf) * SBUF;

#pragma unroll
        for (int ks = 0; ks < 4; ks++) {
            const int kb = ks * 8 + lr;
            float a[4][4];
#pragma unroll
            for (int mf = 0; mf < 4; mf++) {
                const float* p0 = as + (wm * 64 + mf * 16 + lq) * SPAD;
                a[mf][0] = p0[kb];
                a[mf][1] = p0[8 * SPAD + kb];
                a[mf][2] = p0[kb + 4];
                a[mf][3] = p0[8 * SPAD + kb + 4];
            }
            float b[4][2];
#pragma unroll
            for (int nf = 0; nf < 4; nf++) {
                const float* p0 = bs + (wn * 32 + nf * 8 + lq) * SPAD;
                b[nf][0] = p0[kb];
                b[nf][1] = p0[kb + 4];
            }
#pragma unroll
            for (int mf = 0; mf < 4; mf++)
#pragma unroll
                for (int nf = 0; nf < 4; nf++)
                    mma_tf32(acc[mf][nf], a[mf], b[nf]);
        }
        __syncthreads();
    }

#pragma unroll
    for (int mf = 0; mf < 4; mf++) {
#pragma unroll
        for (int nf = 0; nf < 4; nf++) {
            int r = rowBase + wm * 64 + mf * 16 + lq;
            int c = colBase + wn * 32 + nf * 8 + lr * 2;
            *(float2*)&C[(size_t)r * N + c]       = make_float2(acc[mf][nf][0], acc[mf][nf][1]);
            *(float2*)&C[(size_t)(r + 8) * N + c] = make_float2(acc[mf][nf][2], acc[mf][nf][3]);
        }
    }
}

// ---------------- elementwise tf32 round ----------------------------------------
__global__ void kRound(const float4* __restrict__ src, float4* __restrict__ dst)
{
    int i = blockIdx.x * 256 + threadIdx.x;
    float4 v = src[i];
    v.x = tf32r(v.x); v.y = tf32r(v.y); v.z = tf32r(v.z); v.w = tf32r(v.w);
    dst[i] = v;
}

// ---------------- tiled transpose + round: dst[c][r] = rne(src[r][c]) ------------
__global__ void kTransRound(const float* __restrict__ src, float* __restrict__ dst,
                            int R, int C, size_t sStride, size_t dStride)
{
    __shared__ float t[32][33];
    const float* s = src + blockIdx.z * sStride;
    float* d = dst + blockIdx.z * dStride;
    int c0 = blockIdx.x * 32, r0 = blockIdx.y * 32;
#pragma unroll
    for (int i = 0; i < 32; i += 8) {
        t[threadIdx.y + i][threadIdx.x] = s[(size_t)(r0 + threadIdx.y + i) * C + c0 + threadIdx.x];
    }
    __syncthreads();
#pragma unroll
    for (int i = 0; i < 32; i += 8) {
        d[(size_t)(c0 + threadIdx.y + i) * R + r0 + threadIdx.x] =
            tf32r(t[threadIdx.x][threadIdx.y + i]);
    }
}

// ---------------- s1/s2: warp per (n,h) dot over HD=128 --------------------------
__global__ void kComputeS(const float* __restrict__ Wh, const float* __restrict__ a1,
                          const float* __restrict__ a2, float* s1, float* s2)
{
    int w = (blockIdx.x * blockDim.x + threadIdx.x) >> 5;
    int lane = threadIdx.x & 31;
    int n = w >> 3, h = w & 7;
    float4 v  = *(const float4*)(Wh + (size_t)n * GH + h * HDIM + lane * 4);
    float4 x1 = *(const float4*)(a1 + h * HDIM + lane * 4);
    float4 x2 = *(const float4*)(a2 + h * HDIM + lane * 4);
    float d1 = v.x * x1.x + v.y * x1.y + v.z * x1.z + v.w * x1.w;
    float d2 = v.x * x2.x + v.y * x2.y + v.z * x2.z + v.w * x2.w;
#pragma unroll
    for (int o = 16; o; o >>= 1) {
        d1 += __shfl_xor_sync(~0u, d1, o);
        d2 += __shfl_xor_sync(~0u, d2, o);
    }
    if (!lane) { s1[h * NNODE + n] = d1; s2[h * NNODE + n] = d2; }
}

// ---------------- CSR build ------------------------------------------------------
__global__ void kCsrCount(const float* __restrict__ adj, int* cnt)
{
    int w = (blockIdx.x * blockDim.x + threadIdx.x) >> 5;
    int lane = threadIdx.x & 31;
    if (w >= NNODE) return;
    int c = 0;
    for (int j = lane; j < NNODE; j += 32) c += (adj[(size_t)w * NNODE + j] > 0.f);
#pragma unroll
    for (int o = 16; o; o >>= 1) c += __shfl_xor_sync(~0u, c, o);
    if (!lane) cnt[w] = c;
}

__global__ void kScan(const int* __restrict__ cnt, int* off)
{
    __shared__ int sh[257];
    int t = threadIdx.x;
    int base = t * 8;
    int local[8], s = 0;
#pragma unroll
    for (int i = 0; i < 8; i++) { local[i] = cnt[base + i]; s += local[i]; }
    sh[t] = s;
    __syncthreads();
    if (t == 0) {
        int run = 0;
        for (int i = 0; i < 256; i++) { int v = sh[i]; sh[i] = run; run += v; }
        sh[256] = run;
    }
    __syncthreads();
    int run = sh[t];
#pragma unroll
    for (int i = 0; i < 8; i++) { off[base + i] = run; run += local[i]; }
    if (t == 255) off[NNODE] = sh[256];
}

__global__ void kCsrFill(const float* __restrict__ adj, const int* __restrict__ off, int* cols)
{
    int w = (blockIdx.x * blockDim.x + threadIdx.x) >> 5;
    int lane = threadIdx.x & 31;
    if (w >= NNODE) return;
    int base = off[w];
    for (int c0 = 0; c0 < NNODE; c0 += 32) {
        bool p = adj[(size_t)w * NNODE + c0 + lane] > 0.f;
        unsigned m = __ballot_sync(~0u, p);
        if (p) cols[base + __popc(m & ((1u << lane) - 1u))] = c0 + lane;
        base += __popc(m);
    }
}

// ---------------- sparse GAT attention: warp h of block n ------------------------
__global__ void kAttn(const float* __restrict__ Wh, const float* __restrict__ s1,
                      const float* __restrict__ s2, const int* __restrict__ off,
                      const int* __restrict__ cols, float* __restrict__ out)
{
    int n = blockIdx.x;
    int h = threadIdx.x >> 5, lane = threadIdx.x & 31;
    int o0 = off[n], o1 = off[n + 1];
    float sv = s1[h * NNODE + n];

    float mx = -INFINITY;
    for (int i = o0 + lane; i < o1; i += 32) {
        float e = sv + s2[h * NNODE + cols[i]];
        e = e > 0.f ? e : 0.2f * e;
        mx = fmaxf(mx, e);
    }
#pragma unroll
    for (int o = 16; o; o >>= 1) mx = fmaxf(mx, __shfl_xor_sync(~0u, mx, o));

    float a0 = 0.f, a1 = 0.f, a2 = 0.f, a3 = 0.f, sum = 0.f;
    for (int i = o0; i < o1; i++) {
        int j = cols[i];
        float e = sv + s2[h * NNODE + j];
        e = e > 0.f ? e : 0.2f * e;
        float wgt = expf(e - mx);
        sum += wgt;
        float4 v = *(const float4*)(Wh + (size_t)j * GH + h * HDIM + lane * 4);
        a0 = fmaf(wgt, v.x, a0); a1 = fmaf(wgt, v.y, a1);
        a2 = fmaf(wgt, v.z, a2); a3 = fmaf(wgt, v.w, a3);
    }
    float inv = 1.f / sum;
    float4 r = make_float4(a0 * inv, a1 * inv, a2 * inv, a3 * inv);
    *(float4*)(out + (size_t)n * GH + h * HDIM + lane * 4) = r;
}

// ---------------- block reduce helper --------------------------------------------
__device__ __forceinline__ float blockReduceSum(float v, float* red)
{
    int t = threadIdx.x;
    red[t] = v; __syncthreads();
    for (int st = 128; st; st >>= 1) { if (t < st) red[t] += red[t + st]; __syncthreads(); }
    float r = red[0];
    __syncthreads();
    return r;
}

// x += elu(layernorm(hin)); row per block, 256 threads
__global__ void kLnEluRes(const float* __restrict__ hin, const float* __restrict__ g,
                          const float* __restrict__ b, float* __restrict__ x)
{
    __shared__ float red[256];
    int n = blockIdx.x, t = threadIdx.x;
    float4 v = ((const float4*)(hin + (size_t)n * GH))[t];
    float mu = blockReduceSum(v.x + v.y + v.z + v.w, red) * (1.f / GH);
    float dx0 = v.x - mu, dx1 = v.y - mu, dx2 = v.z - mu, dx3 = v.w - mu;
    float var = blockReduceSum(dx0*dx0 + dx1*dx1 + dx2*dx2 + dx3*dx3, red) * (1.f / GH);
    float rs = rsqrtf(var + 1e-5f);
    int c = t * 4;
    float4 gg = *(const float4*)(g + c), bb = *(const float4*)(b + c);
    float y0 = dx0 * rs * gg.x + bb.x, y1 = dx1 * rs * gg.y + bb.y;
    float y2 = dx2 * rs * gg.z + bb.z, y3 = dx3 * rs * gg.w + bb.w;
    y0 = y0 > 0.f ? y0 : expm1f(y0); y1 = y1 > 0.f ? y1 : expm1f(y1);
    y2 = y2 > 0.f ? y2 : expm1f(y2); y3 = y3 > 0.f ? y3 : expm1f(y3);
    float4* xp = (float4*)(x + (size_t)n * GH) + t;
    float4 xv = *xp;
    xv.x += y0; xv.y += y1; xv.z += y2; xv.w += y3;
    *xp = xv;
}

// out = rne(gelu(layernorm(C + b1; g, beta)))  (output feeds a tf32 GEMM)
__global__ void kLnGelu(const float* __restrict__ C, const float* __restrict__ b1,
                        const float* __restrict__ g, const float* __restrict__ beta,
                        float* __restrict__ out)
{
    __shared__ float red[256];
    int n = blockIdx.x, t = threadIdx.x;
    int c = t * 4;
    float4 v = ((const float4*)(C + (size_t)n * ED))[t];
    float4 bv = *(const float4*)(b1 + c);
    v.x += bv.x; v.y += bv.y; v.z += bv.z; v.w += bv.w;
    float mu = blockReduceSum(v.x + v.y + v.z + v.w, red) * (1.f / ED);
    float d0 = v.x - mu, d1 = v.y - mu, d2 = v.z - mu, d3 = v.w - mu;
    float var = blockReduceSum(d0*d0 + d1*d1 + d2*d2 + d3*d3, red) * (1.f / ED);
    float rs = rsqrtf(var + 1e-5f);
    float4 gg = *(const float4*)(g + c), be = *(const float4*)(beta + c);
    float y0 = d0 * rs * gg.x + be.x, y1 = d1 * rs * gg.y + be.y;
    float y2 = d2 * rs * gg.z + be.z, y3 = d3 * rs * gg.w + be.w;
    const float k = 0.70710678118654752f;
    y0 = 0.5f * y0 * (1.f + erff(y0 * k)); y1 = 0.5f * y1 * (1.f + erff(y1 * k));
    y2 = 0.5f * y2 * (1.f + erff(y2 * k)); y3 = 0.5f * y3 * (1.f + erff(y3 * k));
    ((float4*)(out + (size_t)n * ED))[t] =
        make_float4(tf32r(y0), tf32r(y1), tf32r(y2), tf32r(y3));
}

// out = rne(l2norm(C + b2)); row per block (output feeds the tf32 sim GEMM)
__global__ void kBiasL2(const float* __restrict__ C, const float* __restrict__ b2,
                        float* __restrict__ out)
{
    __shared__ float red[256];
    int n = blockIdx.x, t = threadIdx.x;
    int c = t * 4;
    float4 v = ((const float4*)(C + (size_t)n * ED))[t];
    float4 bv = *(const float4*)(b2 + c);
    v.x += bv.x; v.y += bv.y; v.z += bv.z; v.w += bv.w;
    float ss = blockReduceSum(v.x*v.x + v.y*v.y + v.z*v.z + v.w*v.w, red);
    float inv = 1.f / fmaxf(sqrtf(ss), 1e-12f);
    ((float4*)(out + (size_t)n * ED))[t] =
        make_float4(tf32r(v.x*inv), tf32r(v.y*inv), tf32r(v.z*inv), tf32r(v.w*inv));
}

// ge = C + pob
__global__ void kBiasAdd(const float* __restrict__ C, const float* __restrict__ bias,
                         float* __restrict__ out, int ncols, int total)
{
    int i = blockIdx.x * 256 + threadIdx.x;
    if (i < total) out[i] = C[i] + bias[i % ncols];
}

// rowv[i] = logsumexp([pos_i, neg_i,:]/T) - pos_i/T
__global__ void kLse(const float* __restrict__ neg, float* __restrict__ rowv)
{
    __shared__ float red[256];
    int i = blockIdx.x, t = threadIdx.x;
    const float invT = 1.f / TEMPR;
    float pos = neg[(size_t)i * BB + i] * invT;
    float4 v = ((const float4*)(neg + (size_t)i * BB))[t];
    v.x *= invT; v.y *= invT; v.z *= invT; v.w *= invT;
    float m = fmaxf(fmaxf(v.x, v.y), fmaxf(v.z, v.w));
    m = fmaxf(m, pos);
    red[t] = m; __syncthreads();
    for (int st = 128; st; st >>= 1) { if (t < st) red[t] = fmaxf(red[t], red[t + st]); __syncthreads(); }
    float M = red[0];
    __syncthreads();
    float s = expf(v.x - M) + expf(v.y - M) + expf(v.z - M) + expf(v.w - M);
    float S = blockReduceSum(s, red);
    if (t == 0) rowv[i] = M + logf(S + expf(pos - M)) - pos;
}

__global__ void kMeanRow(const float* __restrict__ rowv, float* scal)
{
    __shared__ float red[256];
    int t = threadIdx.x;
    float s = rowv[t] + rowv[t + 256] + rowv[t + 512] + rowv[t + 768];
    float S = blockReduceSum(s, red);
    if (t == 0) scal[0] = S / (float)BB;
}

__global__ void kDotPart(const float* __restrict__ a, const float* __restrict__ b,
                         float* part, int n)
{
    __shared__ float red[256];
    float s = 0.f;
    for (int i = blockIdx.x * 256 + threadIdx.x; i < n; i += 256 * 256) s = fmaf(a[i], b[i], s);
    float S = blockReduceSum(s, red);
    if (threadIdx.x == 0) part[blockIdx.x] = S;
}

__global__ void kDotFinal(const float* __restrict__ part, float* scal)
{
    __shared__ float red[256];
    float S = blockReduceSum(part[threadIdx.x], red);
    if (threadIdx.x == 0) scal[1] = S / (float)NNODE;
}

__global__ void kFinal(const float* __restrict__ scal, float* out, int n)
{
    if (threadIdx.x == 0) {
        float inf_nce = scal[0], lap = scal[1];
        if (n > 0) out[0] = inf_nce + LAPW * lap;
        if (n > 1) out[1] = inf_nce;
        if (n > 2) out[2] = lap;
    }
}

// ---------------- host -----------------------------------------------------------
static inline void* sym(const void* s) { void* p = nullptr; cudaGetSymbolAddress(&p, s); return p; }

static void gemm(const float* A, const float* Bt, float* C, int M, int N, int K)
{
    dim3 grid(N / BN, M / BM);
    gemm_tf32<<<grid, 256, GEMM_SMEM>>>(A, Bt, C, M, N, K);
}

extern "C" void kernel_launch(void* const* d_in, const int* in_sizes, int n_in,
                              void* d_out, int out_size)
{
    const float* query = (const float*)d_in[0];
    const float* docs  = (const float*)d_in[1];
    const float* nodes = (const float*)d_in[2];
    const float* adj   = (const float*)d_in[3];
    const float* lapM  = (const float*)d_in[4];
    const float* qW1 = (const float*)d_in[5];  const float* qb1 = (const float*)d_in[6];
    const float* qg  = (const float*)d_in[7];  const float* qbt = (const float*)d_in[8];
    const float* qW2 = (const float*)d_in[9];  const float* qb2 = (const float*)d_in[10];
    const float* dW1 = (const float*)d_in[11]; const float* db1 = (const float*)d_in[12];
    const float* dg  = (const float*)d_in[13]; const float* dbt = (const float*)d_in[14];
    const float* dW2 = (const float*)d_in[15]; const float* db2 = (const float*)d_in[16];
    const float* gatW = (const float*)d_in[17];
    const float* a1 = (const float*)d_in[18];
    const float* a2 = (const float*)d_in[19];
    const float* ln_g = (const float*)d_in[20];
    const float* ln_b = (const float*)d_in[21];
    const float* poW = (const float*)d_in[22];
    const float* pob = (const float*)d_in[23];

    float* x    = (float*)sym(g_x);
    float* xr   = (float*)sym(g_xr);
    float* Wh   = (float*)sym(g_Wh);
    float* Wcat = (float*)sym(g_Wcat);
    float* wT   = (float*)sym(g_wT);
    float* lapr = (float*)sym(g_lapr);
    float* geT  = (float*)sym(g_geT);
    float* s1   = (float*)sym(g_s1);
    float* s2   = (float*)sym(g_s2);
    float* hb   = (float*)sym(g_hb);
    int*   cnt  = (int*)sym(g_cnt);
    int*   off  = (int*)sym(g_off);
    int*   cols = (int*)sym(g_cols);
    float* ge   = (float*)sym(g_ge);
    float* tb   = (float*)sym(g_t);
    float* tmp1 = (float*)sym(g_tmp1);
    float* tmp2 = (float*)sym(g_tmp2);
    float* q    = (float*)sym(g_q);
    float* p    = (float*)sym(g_p);
    float* neg  = (float*)sym(g_neg);
    float* rowv = (float*)sym(g_rowv);
    float* part = (float*)sym(g_part);
    float* scal = (float*)sym(g_scal);

    cudaFuncSetAttribute(gemm_tf32, cudaFuncAttributeMaxDynamicSharedMemorySize, GEMM_SMEM);

    // init node state
    cudaMemcpyAsync(x, nodes, (size_t)NNODE * ED * sizeof(float), cudaMemcpyDeviceToDevice);

    // CSR from adj
    kCsrCount<<<NNODE / 8, 256>>>(adj, cnt);
    kScan<<<1, 256>>>(cnt, off);
    kCsrFill<<<NNODE / 8, 256>>>(adj, off, cols);

    // round laplacian once (A operand of the lap GEMM)
    kRound<<<(NNODE * NNODE) / 1024, 256>>>((const float4*)lapM, (float4*)lapr);

    dim3 tb32(32, 8);

    for (int l = 0; l < NLAY; l++) {
        // WcatT[h*128+o][f] = rne(gatW[l][h][f][o]) : batch-transpose 8 heads
        kTransRound<<<dim3(HDIM / 32, ED / 32, NHEAD), tb32>>>(
            gatW + (size_t)l * NHEAD * ED * HDIM, Wcat, ED, HDIM,
            (size_t)ED * HDIM, (size_t)HDIM * ED);
        kRound<<<(NNODE * GH) / 1024, 256>>>((const float4*)x, (float4*)xr);
        gemm(xr, Wcat, Wh, NNODE, GH, ED);
        kComputeS<<<(NNODE * NHEAD) / 8, 256>>>(Wh, a1 + (size_t)l * NHEAD * HDIM,
                                                a2 + (size_t)l * NHEAD * HDIM, s1, s2);
        kAttn<<<NNODE, 256>>>(Wh, s1, s2, off, cols, hb);
        kLnEluRes<<<NNODE, 256>>>(hb, ln_g + (size_t)l * GH, ln_b + (size_t)l * GH, x);
    }

    // graph embeds = x @ poW + pob
    kTransRound<<<dim3(ED / 32, GH / 32), tb32>>>(poW, wT, GH, ED, 0, 0);
    kRound<<<(NNODE * GH) / 1024, 256>>>((const float4*)x, (float4*)xr);
    gemm(xr, wT, tb, NNODE, ED, GH);
    kBiasAdd<<<(NNODE * ED) / 256, 256>>>(tb, pob, ge, ED, NNODE * ED);

    // query tower
    kRound<<<(BB * ED) / 1024, 256>>>((const float4*)query, (float4*)xr);
    kTransRound<<<dim3(ED / 32, ED / 32), tb32>>>(qW1, wT, ED, ED, 0, 0);
    gemm(xr, wT, tmp1, BB, ED, ED);
    kLnGelu<<<BB, 256>>>(tmp1, qb1, qg, qbt, tmp2);
    kTransRound<<<dim3(ED / 32, ED / 32), tb32>>>(qW2, wT, ED, ED, 0, 0);
    gemm(tmp2, wT, tmp1, BB, ED, ED);
    kBiasL2<<<BB, 256>>>(tmp1, qb2, q);

    // doc tower
    kRound<<<(BB * ED) / 1024, 256>>>((const float4*)docs, (float4*)xr);
    kTransRound<<<dim3(ED / 32, ED / 32), tb32>>>(dW1, wT, ED, ED, 0, 0);
    gemm(xr, wT, tmp1, BB, ED, ED);
    kLnGelu<<<BB, 256>>>(tmp1, db1, dg, dbt, tmp2);
    kTransRound<<<dim3(ED / 32, ED / 32), tb32>>>(dW2, wT, ED, ED, 0, 0);
    gemm(tmp2, wT, tmp1, BB, ED, ED);
    kBiasL2<<<BB, 256>>>(tmp1, db2, p);

    // similarities + InfoNCE  (q, p already tf32-rounded)
    gemm(q, p, neg, BB, BB, ED);
    kLse<<<BB, 256>>>(neg, rowv);
    kMeanRow<<<1, 256>>>(rowv, scal);

    // laplacian term: t = lap @ ge ; lapsum = sum(ge * t)/N
    kTransRound<<<dim3(ED / 32, NNODE / 32), tb32>>>(ge, geT, NNODE, ED, 0, 0);
    gemm(lapr, geT, tb, NNODE, ED, NNODE);
    kDotPart<<<256, 256>>>(ge, tb, part, NNODE * ED);
    kDotFinal<<<1, 256>>>(part, scal);

    kFinal<<<1, 32>>>(scal, (float*)d_out, out_size);
}